// round 16
// baseline (speedup 1.0000x reference)
#include <cuda_runtime.h>
#include <cuda_bf16.h>
#include <cuda_fp16.h>
#include <cstdint>

#define NNODE 20000
#define DDEG  16

typedef unsigned long long ull;

// ---------------- scratch (device globals; no allocations) ----------------
__device__ __half g_Xp[(size_t)NNODE * 512];  // input projection (+bias), fp16
__device__ float  g_H[(size_t)NNODE * 128];   // LSTM final hidden
__device__ float  g_h1[(size_t)NNODE * 128];  // layer-1 output

// ---------------- math helpers ----------------
__device__ __forceinline__ float tanh_f(float x) {
    float y; asm("tanh.approx.f32 %0, %1;" : "=f"(y) : "f"(x)); return y;
}
__device__ __forceinline__ float sig_f(float x) {
    return fmaf(0.5f, tanh_f(0.5f * x), 0.5f);
}
__device__ __forceinline__ float sig_exact(float x) { return 1.f / (1.f + __expf(-x)); }

// pack two fp32 -> bf16x2 (lo in low half)
__device__ __forceinline__ uint32_t bf16x2_pack(float hi, float lo) {
    uint32_t r; asm("cvt.rn.bf16x2.f32 %0, %1, %2;" : "=r"(r) : "f"(hi), "f"(lo)); return r;
}

// Ampere-class bf16 tensor-core MMA (baseline PTX; runs on sm_103 fallback HMMA)
__device__ __forceinline__ void mma_bf16(float* d, const uint32_t* a, uint32_t b0, uint32_t b1) {
    asm volatile(
        "mma.sync.aligned.m16n8k16.row.col.f32.bf16.bf16.f32 "
        "{%0,%1,%2,%3}, {%4,%5,%6,%7}, {%8,%9}, {%0,%1,%2,%3};"
        : "+f"(d[0]), "+f"(d[1]), "+f"(d[2]), "+f"(d[3])
        : "r"(a[0]), "r"(a[1]), "r"(a[2]), "r"(a[3]), "r"(b0), "r"(b1));
}

#define NWARP   9
#define NODES_B (NWARP * 16)          // 144

// ---------------- HMMA projection GEMM ----------------
// Xp[N,512] = fp16( bf16(A[N,128]) @ bf16(Wih[512,128])^T + (bih+bhh) )
#define PROJ_SMEM (131072 + 2048)
__global__ void __launch_bounds__(NWARP * 32, 1) hmma_proj_kernel(
    const float* __restrict__ A, const float* __restrict__ Wih,
    const float* __restrict__ bih, const float* __restrict__ bhh,
    __half* __restrict__ Xp)
{
    extern __shared__ char smem[];
    ulonglong2* Bfp  = (ulonglong2*)smem;              // [ks8][ntp32][lane32]
    float*      bsum = (float*)(smem + 131072);        // [512]

    const int tid = threadIdx.x;
    const int lane = tid & 31, w = tid >> 5;
    const int gr = lane >> 2, tq = lane & 3;
    const int NT = NWARP * 32;

    for (int i = tid; i < 8192; i += NT) {       // i = ks*1024 + ntp*32 + lane
        int l = i & 31, ntp = (i >> 5) & 31, ks = i >> 10;
        int k0 = ks * 16 + 2 * (l & 3);
        ull fr[2];
#pragma unroll
        for (int h = 0; h < 2; ++h) {
            int n = (2 * ntp + h) * 8 + (l >> 2);
            const float* wr = Wih + (size_t)n * 128;
            float2 p0 = *(const float2*)(wr + k0);
            float2 p1 = *(const float2*)(wr + k0 + 8);
            fr[h] = ((ull)bf16x2_pack(p1.y, p1.x) << 32) | bf16x2_pack(p0.y, p0.x);
        }
        ulonglong2 v; v.x = fr[0]; v.y = fr[1];
        Bfp[i] = v;
    }
    for (int i = tid; i < 512; i += NT) bsum[i] = bih[i] + bhh[i];
    __syncthreads();

    const int r0 = blockIdx.x * NODES_B + w * 16 + gr;
    const int r1 = r0 + 8;
    const float* a0 = A + (size_t)((r0 < NNODE) ? r0 : NNODE - 1) * 128;
    const float* a1 = A + (size_t)((r1 < NNODE) ? r1 : NNODE - 1) * 128;

    uint32_t a[8][4];
#pragma unroll
    for (int ks = 0; ks < 8; ++ks) {
        int k0 = ks * 16 + 2 * tq;
        float2 q;
        q = *(const float2*)(a0 + k0);     a[ks][0] = bf16x2_pack(q.y, q.x);
        q = *(const float2*)(a1 + k0);     a[ks][1] = bf16x2_pack(q.y, q.x);
        q = *(const float2*)(a0 + k0 + 8); a[ks][2] = bf16x2_pack(q.y, q.x);
        q = *(const float2*)(a1 + k0 + 8); a[ks][3] = bf16x2_pack(q.y, q.x);
    }

#pragma unroll
    for (int c = 0; c < 8; ++c) {            // 64-col chunks
        float d[8][4];
#pragma unroll
        for (int m = 0; m < 8; m++)
#pragma unroll
            for (int p = 0; p < 4; p++) d[m][p] = 0.f;
#pragma unroll
        for (int ks = 0; ks < 8; ++ks) {
#pragma unroll
            for (int jp = 0; jp < 4; ++jp) {
                ulonglong2 bb = Bfp[ks * 1024 + (c * 4 + jp) * 32 + lane];
                mma_bf16(d[2 * jp],     a[ks], (uint32_t)bb.x, (uint32_t)(bb.x >> 32));
                mma_bf16(d[2 * jp + 1], a[ks], (uint32_t)bb.y, (uint32_t)(bb.y >> 32));
            }
        }
#pragma unroll
        for (int m = 0; m < 8; ++m) {
            int col = c * 64 + m * 8 + 2 * tq;
            float2 bv = *(const float2*)(bsum + col);
            if (r0 < NNODE)
                *(__half2*)(Xp + (size_t)r0 * 512 + col) =
                    __floats2half2_rn(d[m][0] + bv.x, d[m][1] + bv.y);
            if (r1 < NNODE)
                *(__half2*)(Xp + (size_t)r1 * 512 + col) =
                    __floats2half2_rn(d[m][2] + bv.x, d[m][3] + bv.y);
        }
    }
}

// ---------------- HMMA combine: h1 = relu(x@Wself^T + H@Wneigh^T + b) -----
#define CMB_SMEM (65536 + 512)
__global__ void __launch_bounds__(NWARP * 32, 1) hmma_combine_kernel(
    const float* __restrict__ x, const float* __restrict__ H,
    const float* __restrict__ Wself, const float* __restrict__ Wneigh,
    const float* __restrict__ b, float* __restrict__ h1)
{
    extern __shared__ char smem[];
    ulonglong2* Bfp  = (ulonglong2*)smem;              // [set2][ks8][ntp8][lane32]
    float*      bs   = (float*)(smem + 65536);         // [128]

    const int tid = threadIdx.x;
    const int lane = tid & 31, w = tid >> 5;
    const int gr = lane >> 2, tq = lane & 3;
    const int NT = NWARP * 32;

    for (int i = tid; i < 4096; i += NT) {
        int set = i >> 11, rem = i & 2047;
        int ks = rem >> 8, ntp = (rem >> 5) & 7, l = rem & 31;
        const float* W = set ? Wneigh : Wself;
        int k0 = ks * 16 + 2 * (l & 3);
        ull fr[2];
#pragma unroll
        for (int h = 0; h < 2; ++h) {
            int n = (2 * ntp + h) * 8 + (l >> 2);
            const float* wr = W + (size_t)n * 128;
            float2 p0 = *(const float2*)(wr + k0);
            float2 p1 = *(const float2*)(wr + k0 + 8);
            fr[h] = ((ull)bf16x2_pack(p1.y, p1.x) << 32) | bf16x2_pack(p0.y, p0.x);
        }
        ulonglong2 v; v.x = fr[0]; v.y = fr[1];
        Bfp[i] = v;
    }
    for (int i = tid; i < 128; i += NT) bs[i] = b[i];
    __syncthreads();

    const int r0 = blockIdx.x * NODES_B + w * 16 + gr;
    const int r1 = r0 + 8;
    const int cr0 = (r0 < NNODE) ? r0 : NNODE - 1;
    const int cr1 = (r1 < NNODE) ? r1 : NNODE - 1;

    float d[16][4];
#pragma unroll
    for (int m = 0; m < 16; m++)
#pragma unroll
        for (int p = 0; p < 4; p++) d[m][p] = 0.f;

#pragma unroll
    for (int pass = 0; pass < 2; ++pass) {
        const float* A = pass ? H : x;
        const float* a0 = A + (size_t)cr0 * 128;
        const float* a1 = A + (size_t)cr1 * 128;
        uint32_t a[8][4];
#pragma unroll
        for (int ks = 0; ks < 8; ++ks) {
            int k0 = ks * 16 + 2 * tq;
            float2 q;
            q = *(const float2*)(a0 + k0);     a[ks][0] = bf16x2_pack(q.y, q.x);
            q = *(const float2*)(a1 + k0);     a[ks][1] = bf16x2_pack(q.y, q.x);
            q = *(const float2*)(a0 + k0 + 8); a[ks][2] = bf16x2_pack(q.y, q.x);
            q = *(const float2*)(a1 + k0 + 8); a[ks][3] = bf16x2_pack(q.y, q.x);
        }
#pragma unroll
        for (int ks = 0; ks < 8; ++ks) {
#pragma unroll
            for (int jp = 0; jp < 8; ++jp) {
                ulonglong2 bb = Bfp[pass * 2048 + ks * 256 + jp * 32 + lane];
                mma_bf16(d[2 * jp],     a[ks], (uint32_t)bb.x, (uint32_t)(bb.x >> 32));
                mma_bf16(d[2 * jp + 1], a[ks], (uint32_t)bb.y, (uint32_t)(bb.y >> 32));
            }
        }
    }
#pragma unroll
    for (int m = 0; m < 16; ++m) {
        int col = m * 8 + 2 * tq;
        float2 bv = *(const float2*)(bs + col);
        if (r0 < NNODE)
            *(float2*)(h1 + (size_t)r0 * 128 + col) =
                make_float2(fmaxf(d[m][0] + bv.x, 0.f), fmaxf(d[m][1] + bv.y, 0.f));
        if (r1 < NNODE)
            *(float2*)(h1 + (size_t)r1 * 128 + col) =
                make_float2(fmaxf(d[m][2] + bv.x, 0.f), fmaxf(d[m][3] + bv.y, 0.f));
    }
}

// ---------------- HMMA LSTM layer: 18 warps, unit-split warp pairs --------
// Block = 144 nodes, 576 threads. Warp pair (g, g+9) shares node rows
// [16g,16g+16): warp g computes units 0-63, warp g+9 units 64-127.
// Each warp: 256 MMAs/step (half), half the MUFU epilogue, half the gathers.
// A-frags per node group; pair writes disjoint ks halves, both read all ks
// -> one __syncthreads per step. d-scratch kept at 32 regs via jp-chunking.
#define SM_BF   0
#define SM_AF   131072
#define SM_IDX  (131072 + 73728)
#define LSTM_SMEM (131072 + 73728 + 9216)
__global__ void __launch_bounds__(576, 1) lstm_mma_kernel(
    const __half* __restrict__ Xp, const int* __restrict__ nbr,
    const float* __restrict__ Whh, float* __restrict__ Hout)
{
    extern __shared__ char smem[];
    ulonglong2* Bfp  = (ulonglong2*)(smem + SM_BF);   // [ks8][ntp32][lane32]
    uint32_t*   Af   = (uint32_t*)(smem + SM_AF);     // [buf2][grp9][ks8][lane32][slot4]
    int*        idx_s= (int*)(smem + SM_IDX);         // [144][16]

    const int tid = threadIdx.x;
    const int lane = tid & 31, w = tid >> 5;
    const int g = (w >= 9) ? w - 9 : w;     // node group 0..8
    const int uh2 = (w >= 9) ? 1 : 0;       // unit half: 0 -> units 0-63, 1 -> 64-127
    const int gr = lane >> 2, tq = lane & 3;
    const int nodeBase = blockIdx.x * NODES_B;
    const int NT = 576;

    // ---- pack B = Whh into pair fragments (shared by all warps) ----
    for (int i = tid; i < 8192; i += NT) {
        int l = i & 31, ntp = (i >> 5) & 31, ks = i >> 10;
        int k0 = ks * 16 + 2 * (l & 3);
        ull fr[2];
#pragma unroll
        for (int h = 0; h < 2; ++h) {
            int n = (2 * ntp + h) * 8 + (l >> 2);
            const float* wr = Whh + (size_t)n * 128;
            float2 p0 = *(const float2*)(wr + k0);
            float2 p1 = *(const float2*)(wr + k0 + 8);
            fr[h] = ((ull)bf16x2_pack(p1.y, p1.x) << 32) | bf16x2_pack(p0.y, p0.x);
        }
        ulonglong2 v; v.x = fr[0]; v.y = fr[1];
        Bfp[i] = v;
    }
    for (int i = tid; i < NODES_B * 16; i += NT) {
        int node = nodeBase + (i >> 4);
        idx_s[i] = (node < NNODE) ? nbr[(size_t)node * DDEG + (i & 15)] : 0;
    }
    __syncthreads();

    const int node0 = nodeBase + g * 16 + gr;
    const int node1 = node0 + 8;
    float c[2][2][2][4];                    // [uc2][jp][jin][p]
#pragma unroll
    for (int a = 0; a < 2; a++)
#pragma unroll
        for (int b = 0; b < 2; b++)
#pragma unroll
            for (int e = 0; e < 2; e++)
#pragma unroll
                for (int p = 0; p < 4; p++) c[a][b][e][p] = 0.f;

#pragma unroll 1
    for (int t = 0; t < DDEG; ++t) {
        if (t > 0) __syncthreads();   // pair's A-frag writes (step t-1) visible; buffers safe
        const __half* x0 = Xp + (size_t)idx_s[(g * 16 + gr) * DDEG + t] * 512;
        const __half* x1 = Xp + (size_t)idx_s[(g * 16 + gr + 8) * DDEG + t] * 512;
        uint32_t* Ard = Af + ((t & 1) ^ 1) * (9 * 1024) + g * 1024;
        uint32_t* Awr = Af + (t & 1) * (9 * 1024) + g * 1024;

#pragma unroll
        for (int uc2 = 0; uc2 < 2; ++uc2) {
            const int uca = uh2 * 2 + uc2;           // absolute 32-unit chunk 0..3
#pragma unroll
            for (int jp = 0; jp < 2; ++jp) {
                // ---- hoisted fp16 gathers for j = 2jp, 2jp+1 ----
                __half2 xv[4][2][2];                 // [gate][jin][row01]
#pragma unroll
                for (int jin = 0; jin < 2; ++jin) {
                    int u0 = uca * 32 + (2 * jp + jin) * 8 + 2 * tq;
                    xv[0][jin][0] = *(const __half2*)(x0 + u0);
                    xv[0][jin][1] = *(const __half2*)(x1 + u0);
                    xv[1][jin][0] = *(const __half2*)(x0 + 128 + u0);
                    xv[1][jin][1] = *(const __half2*)(x1 + 128 + u0);
                    xv[2][jin][0] = *(const __half2*)(x0 + 256 + u0);
                    xv[2][jin][1] = *(const __half2*)(x1 + 256 + u0);
                    xv[3][jin][0] = *(const __half2*)(x0 + 384 + u0);
                    xv[3][jin][1] = *(const __half2*)(x1 + 384 + u0);
                }

                float d[4][2][4];                    // [gate][jin][p]
#pragma unroll
                for (int gt = 0; gt < 4; gt++)
#pragma unroll
                    for (int e = 0; e < 2; e++)
#pragma unroll
                        for (int p = 0; p < 4; p++) d[gt][e][p] = 0.f;

                if (t > 0) {
#pragma unroll
                    for (int ks = 0; ks < 8; ++ks) {
                        uint4 av = *(uint4*)(Ard + ks * 128 + lane * 4);
                        uint32_t a[4] = {av.x, av.y, av.z, av.w};
#pragma unroll
                        for (int gt = 0; gt < 4; ++gt) {
                            int ntp = gt * 8 + uca * 2 + jp;
                            ulonglong2 bb = Bfp[ks * 1024 + ntp * 32 + lane];
                            mma_bf16(d[gt][0], a, (uint32_t)bb.x, (uint32_t)(bb.x >> 32));
                            mma_bf16(d[gt][1], a, (uint32_t)bb.y, (uint32_t)(bb.y >> 32));
                        }
                    }
                }
                // ---- epilogue for j = 2jp, 2jp+1 ----
#pragma unroll
                for (int jin = 0; jin < 2; ++jin) {
                    int j = 2 * jp + jin;
                    int u0 = uca * 32 + j * 8 + 2 * tq;
                    float2 vi0 = __half22float2(xv[0][jin][0]), vi1 = __half22float2(xv[0][jin][1]);
                    float2 vf0 = __half22float2(xv[1][jin][0]), vf1 = __half22float2(xv[1][jin][1]);
                    float2 vg0 = __half22float2(xv[2][jin][0]), vg1 = __half22float2(xv[2][jin][1]);
                    float2 vo0 = __half22float2(xv[3][jin][0]), vo1 = __half22float2(xv[3][jin][1]);
                    float gi[4] = {d[0][jin][0] + vi0.x, d[0][jin][1] + vi0.y,
                                   d[0][jin][2] + vi1.x, d[0][jin][3] + vi1.y};
                    float gf[4] = {d[1][jin][0] + vf0.x, d[1][jin][1] + vf0.y,
                                   d[1][jin][2] + vf1.x, d[1][jin][3] + vf1.y};
                    float gg[4] = {d[2][jin][0] + vg0.x, d[2][jin][1] + vg0.y,
                                   d[2][jin][2] + vg1.x, d[2][jin][3] + vg1.y};
                    float go[4] = {d[3][jin][0] + vo0.x, d[3][jin][1] + vo0.y,
                                   d[3][jin][2] + vo1.x, d[3][jin][3] + vo1.y};
                    float h_[4];
#pragma unroll
                    for (int p = 0; p < 4; ++p) {
                        float cn = sig_f(gf[p]) * c[uc2][jp][jin][p] + sig_f(gi[p]) * tanh_f(gg[p]);
                        c[uc2][jp][jin][p] = cn;
                        h_[p] = sig_f(go[p]) * tanh_f(cn);
                    }
                    if (t < DDEG - 1) {
                        uint32_t lo = bf16x2_pack(h_[1], h_[0]);   // row r
                        uint32_t hi = bf16x2_pack(h_[3], h_[2]);   // row r+8
                        int ks = uca * 2 + jp;
                        int slot = jin * 2;
                        *(ull*)(Awr + ks * 128 + lane * 4 + slot) = ((ull)hi << 32) | lo;
                    } else {
                        if (node0 < NNODE)
                            *(float2*)(Hout + (size_t)node0 * 128 + u0) = make_float2(h_[0], h_[1]);
                        if (node1 < NNODE)
                            *(float2*)(Hout + (size_t)node1 * 128 + u0) = make_float2(h_[2], h_[3]);
                    }
                }
            }
        }
    }
}

// ---------------- final layer-2 combine: OUT=1 + sigmoid ----------------
__global__ void out_kernel(const float* __restrict__ h1, const float* __restrict__ H,
                           const float* __restrict__ Wself, const float* __restrict__ Wneigh,
                           const float* __restrict__ b, float* __restrict__ out, int Nrows)
{
    int gwarp = (blockIdx.x * blockDim.x + threadIdx.x) >> 5;
    int lane = threadIdx.x & 31;
    if (gwarp >= Nrows) return;
    float s = 0.f;
#pragma unroll
    for (int q = 0; q < 4; q++) {
        int k = lane + 32 * q;
        s += h1[(size_t)gwarp * 128 + k] * Wself[k] + H[(size_t)gwarp * 128 + k] * Wneigh[k];
    }
#pragma unroll
    for (int off = 16; off; off >>= 1) s += __shfl_xor_sync(0xFFFFFFFFu, s, off);
    if (lane == 0) out[gwarp] = sig_exact(s + b[0]);
}

// ---------------- launch ----------------
extern "C" void kernel_launch(void* const* d_in, const int* in_sizes, int n_in,
                              void* d_out, int out_size)
{
    const float* x       = (const float*)d_in[0];
    const int*   nbr     = (const int*)d_in[1];
    const float* Wih1    = (const float*)d_in[2];
    const float* Whh1    = (const float*)d_in[3];
    const float* bih1    = (const float*)d_in[4];
    const float* bhh1    = (const float*)d_in[5];
    const float* Wself1  = (const float*)d_in[6];
    const float* Wneigh1 = (const float*)d_in[7];
    const float* bneigh1 = (const float*)d_in[8];
    const float* Wih2    = (const float*)d_in[9];
    const float* Whh2    = (const float*)d_in[10];
    const float* bih2    = (const float*)d_in[11];
    const float* bhh2    = (const float*)d_in[12];
    const float* Wself2  = (const float*)d_in[13];
    const float* Wneigh2 = (const float*)d_in[14];
    const float* bneigh2 = (const float*)d_in[15];
    float* out = (float*)d_out;

    __half* Xp; float *H, *h1;
    cudaGetSymbolAddress((void**)&Xp, g_Xp);
    cudaGetSymbolAddress((void**)&H,  g_H);
    cudaGetSymbolAddress((void**)&h1, g_h1);

    cudaFuncSetAttribute(lstm_mma_kernel,     cudaFuncAttributeMaxDynamicSharedMemorySize, LSTM_SMEM);
    cudaFuncSetAttribute(hmma_proj_kernel,    cudaFuncAttributeMaxDynamicSharedMemorySize, PROJ_SMEM);
    cudaFuncSetAttribute(hmma_combine_kernel, cudaFuncAttributeMaxDynamicSharedMemorySize, CMB_SMEM);

    const int TB = 256;
    const int GRID = (NNODE + NODES_B - 1) / NODES_B;   // 139 <= 148: one wave

    // ---- layer 1 ----
    hmma_proj_kernel<<<GRID, NWARP * 32, PROJ_SMEM>>>(x, Wih1, bih1, bhh1, Xp);
    lstm_mma_kernel<<<GRID, 576, LSTM_SMEM>>>(Xp, nbr, Whh1, H);
    hmma_combine_kernel<<<GRID, NWARP * 32, CMB_SMEM>>>(x, H, Wself1, Wneigh1, bneigh1, h1);

    // ---- layer 2 ----
    hmma_proj_kernel<<<GRID, NWARP * 32, PROJ_SMEM>>>(h1, Wih2, bih2, bhh2, Xp);
    lstm_mma_kernel<<<GRID, 576, LSTM_SMEM>>>(Xp, nbr, Whh2, H);
    out_kernel<<<(NNODE * 32 + TB - 1) / TB, TB>>>(h1, H, Wself2, Wneigh2, bneigh2, out, NNODE);
}

// round 17
// speedup vs baseline: 1.1425x; 1.1425x over previous
#include <cuda_runtime.h>
#include <cuda_fp16.h>
#include <cstdint>

#define NNODE 20000
#define DDEG  16

typedef unsigned long long ull;

// ---------------- scratch (device globals; no allocations) ----------------
__device__ __half g_Xp[(size_t)NNODE * 512];  // input projection (+bias), fp16
__device__ float  g_H[(size_t)NNODE * 128];   // LSTM final hidden
__device__ float  g_h1[(size_t)NNODE * 128];  // layer-1 output

// ---------------- math helpers ----------------
__device__ __forceinline__ float tanh_f(float x) {
    float y; asm("tanh.approx.f32 %0, %1;" : "=f"(y) : "f"(x)); return y;
}
__device__ __forceinline__ float sig_exact(float x) { return 1.f / (1.f + __expf(-x)); }

__device__ __forceinline__ __half2 tanh_h2(__half2 x) {
    uint32_t xi = *(uint32_t*)&x, yi;
    asm("tanh.approx.f16x2 %0, %1;" : "=r"(yi) : "r"(xi));
    return *(__half2*)&yi;
}
// sigmoid(x) = 0.5*tanh(0.5x)+0.5, packed
__device__ __forceinline__ __half2 sig_h2(__half2 x) {
    const __half2 h05 = __floats2half2_rn(0.5f, 0.5f);
    return __hfma2(h05, tanh_h2(__hmul2(h05, x)), h05);
}
// pack two fp32 -> f16x2 (lo in low half)
__device__ __forceinline__ uint32_t f16x2_pack(float hi, float lo) {
    __half2 h = __floats2half2_rn(lo, hi);
    return *(uint32_t*)&h;
}

// Ampere-class fp16 tensor-core MMA (baseline PTX; fallback HMMA on sm_103)
__device__ __forceinline__ void mma_f16(float* d, const uint32_t* a, uint32_t b0, uint32_t b1) {
    asm volatile(
        "mma.sync.aligned.m16n8k16.row.col.f32.f16.f16.f32 "
        "{%0,%1,%2,%3}, {%4,%5,%6,%7}, {%8,%9}, {%0,%1,%2,%3};"
        : "+f"(d[0]), "+f"(d[1]), "+f"(d[2]), "+f"(d[3])
        : "r"(a[0]), "r"(a[1]), "r"(a[2]), "r"(a[3]), "r"(b0), "r"(b1));
}

#define NWARP   9
#define NODES_B (NWARP * 16)          // 144

// ---------------- HMMA projection GEMM ----------------
// Xp[N,512] = fp16( f16(A[N,128]) @ f16(Wih[512,128])^T + (bih+bhh) )
#define PROJ_SMEM (131072 + 2048)
__global__ void __launch_bounds__(NWARP * 32, 1) hmma_proj_kernel(
    const float* __restrict__ A, const float* __restrict__ Wih,
    const float* __restrict__ bih, const float* __restrict__ bhh,
    __half* __restrict__ Xp)
{
    extern __shared__ char smem[];
    ulonglong2* Bfp  = (ulonglong2*)smem;              // [ks8][ntp32][lane32]
    float*      bsum = (float*)(smem + 131072);        // [512]

    const int tid = threadIdx.x;
    const int lane = tid & 31, w = tid >> 5;
    const int gr = lane >> 2, tq = lane & 3;
    const int NT = NWARP * 32;

    for (int i = tid; i < 8192; i += NT) {       // i = ks*1024 + ntp*32 + lane
        int l = i & 31, ntp = (i >> 5) & 31, ks = i >> 10;
        int k0 = ks * 16 + 2 * (l & 3);
        ull fr[2];
#pragma unroll
        for (int h = 0; h < 2; ++h) {
            int n = (2 * ntp + h) * 8 + (l >> 2);
            const float* wr = Wih + (size_t)n * 128;
            float2 p0 = *(const float2*)(wr + k0);
            float2 p1 = *(const float2*)(wr + k0 + 8);
            fr[h] = ((ull)f16x2_pack(p1.y, p1.x) << 32) | f16x2_pack(p0.y, p0.x);
        }
        ulonglong2 v; v.x = fr[0]; v.y = fr[1];
        Bfp[i] = v;
    }
    for (int i = tid; i < 512; i += NT) bsum[i] = bih[i] + bhh[i];
    __syncthreads();

    const int r0 = blockIdx.x * NODES_B + w * 16 + gr;
    const int r1 = r0 + 8;
    const float* a0 = A + (size_t)((r0 < NNODE) ? r0 : NNODE - 1) * 128;
    const float* a1 = A + (size_t)((r1 < NNODE) ? r1 : NNODE - 1) * 128;

    uint32_t a[8][4];
#pragma unroll
    for (int ks = 0; ks < 8; ++ks) {
        int k0 = ks * 16 + 2 * tq;
        float2 q;
        q = *(const float2*)(a0 + k0);     a[ks][0] = f16x2_pack(q.y, q.x);
        q = *(const float2*)(a1 + k0);     a[ks][1] = f16x2_pack(q.y, q.x);
        q = *(const float2*)(a0 + k0 + 8); a[ks][2] = f16x2_pack(q.y, q.x);
        q = *(const float2*)(a1 + k0 + 8); a[ks][3] = f16x2_pack(q.y, q.x);
    }

#pragma unroll
    for (int c = 0; c < 8; ++c) {            // 64-col chunks
        float d[8][4];
#pragma unroll
        for (int m = 0; m < 8; m++)
#pragma unroll
            for (int p = 0; p < 4; p++) d[m][p] = 0.f;
#pragma unroll
        for (int ks = 0; ks < 8; ++ks) {
#pragma unroll
            for (int jp = 0; jp < 4; ++jp) {
                ulonglong2 bb = Bfp[ks * 1024 + (c * 4 + jp) * 32 + lane];
                mma_f16(d[2 * jp],     a[ks], (uint32_t)bb.x, (uint32_t)(bb.x >> 32));
                mma_f16(d[2 * jp + 1], a[ks], (uint32_t)bb.y, (uint32_t)(bb.y >> 32));
            }
        }
#pragma unroll
        for (int m = 0; m < 8; ++m) {
            int col = c * 64 + m * 8 + 2 * tq;
            float2 bv = *(const float2*)(bsum + col);
            if (r0 < NNODE)
                *(__half2*)(Xp + (size_t)r0 * 512 + col) =
                    __floats2half2_rn(d[m][0] + bv.x, d[m][1] + bv.y);
            if (r1 < NNODE)
                *(__half2*)(Xp + (size_t)r1 * 512 + col) =
                    __floats2half2_rn(d[m][2] + bv.x, d[m][3] + bv.y);
        }
    }
}

// ---------------- HMMA combine: h1 = relu(x@Wself^T + H@Wneigh^T + b) -----
#define CMB_SMEM (65536 + 512)
__global__ void __launch_bounds__(NWARP * 32, 1) hmma_combine_kernel(
    const float* __restrict__ x, const float* __restrict__ H,
    const float* __restrict__ Wself, const float* __restrict__ Wneigh,
    const float* __restrict__ b, float* __restrict__ h1)
{
    extern __shared__ char smem[];
    ulonglong2* Bfp  = (ulonglong2*)smem;              // [set2][ks8][ntp8][lane32]
    float*      bs   = (float*)(smem + 65536);         // [128]

    const int tid = threadIdx.x;
    const int lane = tid & 31, w = tid >> 5;
    const int gr = lane >> 2, tq = lane & 3;
    const int NT = NWARP * 32;

    for (int i = tid; i < 4096; i += NT) {
        int set = i >> 11, rem = i & 2047;
        int ks = rem >> 8, ntp = (rem >> 5) & 7, l = rem & 31;
        const float* W = set ? Wneigh : Wself;
        int k0 = ks * 16 + 2 * (l & 3);
        ull fr[2];
#pragma unroll
        for (int h = 0; h < 2; ++h) {
            int n = (2 * ntp + h) * 8 + (l >> 2);
            const float* wr = W + (size_t)n * 128;
            float2 p0 = *(const float2*)(wr + k0);
            float2 p1 = *(const float2*)(wr + k0 + 8);
            fr[h] = ((ull)f16x2_pack(p1.y, p1.x) << 32) | f16x2_pack(p0.y, p0.x);
        }
        ulonglong2 v; v.x = fr[0]; v.y = fr[1];
        Bfp[i] = v;
    }
    for (int i = tid; i < 128; i += NT) bs[i] = b[i];
    __syncthreads();

    const int r0 = blockIdx.x * NODES_B + w * 16 + gr;
    const int r1 = r0 + 8;
    const int cr0 = (r0 < NNODE) ? r0 : NNODE - 1;
    const int cr1 = (r1 < NNODE) ? r1 : NNODE - 1;

    float d[16][4];
#pragma unroll
    for (int m = 0; m < 16; m++)
#pragma unroll
        for (int p = 0; p < 4; p++) d[m][p] = 0.f;

#pragma unroll
    for (int pass = 0; pass < 2; ++pass) {
        const float* A = pass ? H : x;
        const float* a0 = A + (size_t)cr0 * 128;
        const float* a1 = A + (size_t)cr1 * 128;
        uint32_t a[8][4];
#pragma unroll
        for (int ks = 0; ks < 8; ++ks) {
            int k0 = ks * 16 + 2 * tq;
            float2 q;
            q = *(const float2*)(a0 + k0);     a[ks][0] = f16x2_pack(q.y, q.x);
            q = *(const float2*)(a1 + k0);     a[ks][1] = f16x2_pack(q.y, q.x);
            q = *(const float2*)(a0 + k0 + 8); a[ks][2] = f16x2_pack(q.y, q.x);
            q = *(const float2*)(a1 + k0 + 8); a[ks][3] = f16x2_pack(q.y, q.x);
        }
#pragma unroll
        for (int ks = 0; ks < 8; ++ks) {
#pragma unroll
            for (int jp = 0; jp < 8; ++jp) {
                ulonglong2 bb = Bfp[pass * 2048 + ks * 256 + jp * 32 + lane];
                mma_f16(d[2 * jp],     a[ks], (uint32_t)bb.x, (uint32_t)(bb.x >> 32));
                mma_f16(d[2 * jp + 1], a[ks], (uint32_t)bb.y, (uint32_t)(bb.y >> 32));
            }
        }
    }
#pragma unroll
    for (int m = 0; m < 16; ++m) {
        int col = m * 8 + 2 * tq;
        float2 bv = *(const float2*)(bs + col);
        if (r0 < NNODE)
            *(float2*)(h1 + (size_t)r0 * 128 + col) =
                make_float2(fmaxf(d[m][0] + bv.x, 0.f), fmaxf(d[m][1] + bv.y, 0.f));
        if (r1 < NNODE)
            *(float2*)(h1 + (size_t)r1 * 128 + col) =
                make_float2(fmaxf(d[m][2] + bv.x, 0.f), fmaxf(d[m][3] + bv.y, 0.f));
    }
}

// ---------------- HMMA LSTM layer (R14 structure, f16 MMA, half2 epilogue)
// Block = 144 nodes, 9 warps, one wave. Warp w owns rows [16w,16w+16), all
// 512 gate cols. A (h) fragment-ready fp16, double-buffered, same-lane
// write/read -> NO synchronization in the 16-step main loop.
// Epilogue fully packed: gates via cvt.f16x2+HADD2 against fp16 Xp words,
// tanh.approx.f16x2 (half the MUFU ops), c kept fp32, h emitted as the
// A-fragment half2 word directly.
#define SM_BF   0
#define SM_AF   131072
#define SM_IDX  (131072 + 73728)
#define LSTM_SMEM (131072 + 73728 + 9216)
__global__ void __launch_bounds__(NWARP * 32, 1) lstm_mma_kernel(
    const __half* __restrict__ Xp, const int* __restrict__ nbr,
    const float* __restrict__ Whh, float* __restrict__ Hout)
{
    extern __shared__ char smem[];
    ulonglong2* Bfp  = (ulonglong2*)(smem + SM_BF);   // [ks8][ntp32][lane32]
    uint32_t*   Af   = (uint32_t*)(smem + SM_AF);     // [buf2][w9][ks8][lane32][slot4]
    int*        idx_s= (int*)(smem + SM_IDX);         // [144][16]

    const int tid = threadIdx.x;
    const int lane = tid & 31, w = tid >> 5;
    const int gr = lane >> 2, tq = lane & 3;
    const int nodeBase = blockIdx.x * NODES_B;
    const int NT = NWARP * 32;

    for (int i = tid; i < 8192; i += NT) {
        int l = i & 31, ntp = (i >> 5) & 31, ks = i >> 10;
        int k0 = ks * 16 + 2 * (l & 3);
        ull fr[2];
#pragma unroll
        for (int h = 0; h < 2; ++h) {
            int n = (2 * ntp + h) * 8 + (l >> 2);
            const float* wr = Whh + (size_t)n * 128;
            float2 p0 = *(const float2*)(wr + k0);
            float2 p1 = *(const float2*)(wr + k0 + 8);
            fr[h] = ((ull)f16x2_pack(p1.y, p1.x) << 32) | f16x2_pack(p0.y, p0.x);
        }
        ulonglong2 v; v.x = fr[0]; v.y = fr[1];
        Bfp[i] = v;
    }
    for (int i = tid; i < NODES_B * 16; i += NT) {
        int node = nodeBase + (i >> 4);
        idx_s[i] = (node < NNODE) ? nbr[(size_t)node * DDEG + (i & 15)] : 0;
    }
    __syncthreads();

    const int node0 = nodeBase + w * 16 + gr;
    const int node1 = node0 + 8;
    float c[4][4][4];
#pragma unroll
    for (int a = 0; a < 4; a++)
#pragma unroll
        for (int b = 0; b < 4; b++)
#pragma unroll
            for (int p = 0; p < 4; p++) c[a][b][p] = 0.f;

#pragma unroll 1
    for (int t = 0; t < DDEG; ++t) {
        const __half* x0 = Xp + (size_t)idx_s[(w * 16 + gr) * DDEG + t] * 512;
        const __half* x1 = Xp + (size_t)idx_s[(w * 16 + gr + 8) * DDEG + t] * 512;
        uint32_t* Ard = Af + ((t & 1) ^ 1) * (NWARP * 1024) + w * 1024;
        uint32_t* Awr = Af + (t & 1) * (NWARP * 1024) + w * 1024;

#pragma unroll
        for (int uc = 0; uc < 4; ++uc) {
            // ---- hoisted fp16 gathers for this uc ----
            __half2 xi0[4], xf0[4], xg0[4], xo0[4];
            __half2 xi1[4], xf1[4], xg1[4], xo1[4];
#pragma unroll
            for (int j = 0; j < 4; ++j) {
                int u0 = uc * 32 + j * 8 + 2 * tq;
                xi0[j] = *(const __half2*)(x0 + u0);
                xf0[j] = *(const __half2*)(x0 + 128 + u0);
                xg0[j] = *(const __half2*)(x0 + 256 + u0);
                xo0[j] = *(const __half2*)(x0 + 384 + u0);
                xi1[j] = *(const __half2*)(x1 + u0);
                xf1[j] = *(const __half2*)(x1 + 128 + u0);
                xg1[j] = *(const __half2*)(x1 + 256 + u0);
                xo1[j] = *(const __half2*)(x1 + 384 + u0);
            }

            float d[4][4][4];                // [gate][j][p]
#pragma unroll
            for (int g = 0; g < 4; g++)
#pragma unroll
                for (int j = 0; j < 4; j++)
#pragma unroll
                    for (int p = 0; p < 4; p++) d[g][j][p] = 0.f;

            if (t > 0) {
#pragma unroll
                for (int ks = 0; ks < 8; ++ks) {
                    uint4 av = *(uint4*)(Ard + ks * 128 + lane * 4);
                    uint32_t a[4] = {av.x, av.y, av.z, av.w};
#pragma unroll
                    for (int g = 0; g < 4; ++g) {
                        int ntp0 = g * 8 + uc * 2;
#pragma unroll
                        for (int jp = 0; jp < 2; ++jp) {
                            ulonglong2 bb = Bfp[ks * 1024 + (ntp0 + jp) * 32 + lane];
                            mma_f16(d[g][2 * jp],     a, (uint32_t)bb.x, (uint32_t)(bb.x >> 32));
                            mma_f16(d[g][2 * jp + 1], a, (uint32_t)bb.y, (uint32_t)(bb.y >> 32));
                        }
                    }
                }
            }
            // ---- packed epilogue: gates + cell update ----
#pragma unroll
            for (int j = 0; j < 4; ++j) {
                int u0 = uc * 32 + j * 8 + 2 * tq;
                // row r (p = 0,1)
                __half2 gi0 = __hadd2(__floats2half2_rn(d[0][j][0], d[0][j][1]), xi0[j]);
                __half2 gf0 = __hadd2(__floats2half2_rn(d[1][j][0], d[1][j][1]), xf0[j]);
                __half2 gg0 = __hadd2(__floats2half2_rn(d[2][j][0], d[2][j][1]), xg0[j]);
                __half2 go0 = __hadd2(__floats2half2_rn(d[3][j][0], d[3][j][1]), xo0[j]);
                __half2 itg0 = __hmul2(sig_h2(gi0), tanh_h2(gg0));
                float2 sf0 = __half22float2(sig_h2(gf0));
                float2 pv0 = __half22float2(itg0);
                c[uc][j][0] = fmaf(sf0.x, c[uc][j][0], pv0.x);
                c[uc][j][1] = fmaf(sf0.y, c[uc][j][1], pv0.y);
                __half2 h20 = __hmul2(sig_h2(go0),
                                      tanh_h2(__floats2half2_rn(c[uc][j][0], c[uc][j][1])));
                // row r+8 (p = 2,3)
                __half2 gi1 = __hadd2(__floats2half2_rn(d[0][j][2], d[0][j][3]), xi1[j]);
                __half2 gf1 = __hadd2(__floats2half2_rn(d[1][j][2], d[1][j][3]), xf1[j]);
                __half2 gg1 = __hadd2(__floats2half2_rn(d[2][j][2], d[2][j][3]), xg1[j]);
                __half2 go1 = __hadd2(__floats2half2_rn(d[3][j][2], d[3][j][3]), xo1[j]);
                __half2 itg1 = __hmul2(sig_h2(gi1), tanh_h2(gg1));
                float2 sf1 = __half22float2(sig_h2(gf1));
                float2 pv1 = __half22float2(itg1);
                c[uc][j][2] = fmaf(sf1.x, c[uc][j][2], pv1.x);
                c[uc][j][3] = fmaf(sf1.y, c[uc][j][3], pv1.y);
                __half2 h21 = __hmul2(sig_h2(go1),
                                      tanh_h2(__floats2half2_rn(c[uc][j][2], c[uc][j][3])));

                if (t < DDEG - 1) {
                    // h words are already the fp16 A-fragment slots
                    uint32_t lo = *(uint32_t*)&h20;   // row r
                    uint32_t hi = *(uint32_t*)&h21;   // row r+8
                    int ks = uc * 2 + (j >> 1);
                    int slot = (j & 1) * 2;
                    *(ull*)(Awr + ks * 128 + lane * 4 + slot) = ((ull)hi << 32) | lo;
                } else {
                    if (node0 < NNODE)
                        *(float2*)(Hout + (size_t)node0 * 128 + u0) = __half22float2(h20);
                    if (node1 < NNODE)
                        *(float2*)(Hout + (size_t)node1 * 128 + u0) = __half22float2(h21);
                }
            }
        }
    }
}

// ---------------- final layer-2 combine: OUT=1 + sigmoid ----------------
__global__ void out_kernel(const float* __restrict__ h1, const float* __restrict__ H,
                           const float* __restrict__ Wself, const float* __restrict__ Wneigh,
                           const float* __restrict__ b, float* __restrict__ out, int Nrows)
{
    int gwarp = (blockIdx.x * blockDim.x + threadIdx.x) >> 5;
    int lane = threadIdx.x & 31;
    if (gwarp >= Nrows) return;
    float s = 0.f;
#pragma unroll
    for (int q = 0; q < 4; q++) {
        int k = lane + 32 * q;
        s += h1[(size_t)gwarp * 128 + k] * Wself[k] + H[(size_t)gwarp * 128 + k] * Wneigh[k];
    }
#pragma unroll
    for (int off = 16; off; off >>= 1) s += __shfl_xor_sync(0xFFFFFFFFu, s, off);
    if (lane == 0) out[gwarp] = sig_exact(s + b[0]);
}

// ---------------- launch ----------------
extern "C" void kernel_launch(void* const* d_in, const int* in_sizes, int n_in,
                              void* d_out, int out_size)
{
    const float* x       = (const float*)d_in[0];
    const int*   nbr     = (const int*)d_in[1];
    const float* Wih1    = (const float*)d_in[2];
    const float* Whh1    = (const float*)d_in[3];
    const float* bih1    = (const float*)d_in[4];
    const float* bhh1    = (const float*)d_in[5];
    const float* Wself1  = (const float*)d_in[6];
    const float* Wneigh1 = (const float*)d_in[7];
    const float* bneigh1 = (const float*)d_in[8];
    const float* Wih2    = (const float*)d_in[9];
    const float* Whh2    = (const float*)d_in[10];
    const float* bih2    = (const float*)d_in[11];
    const float* bhh2    = (const float*)d_in[12];
    const float* Wself2  = (const float*)d_in[13];
    const float* Wneigh2 = (const float*)d_in[14];
    const float* bneigh2 = (const float*)d_in[15];
    float* out = (float*)d_out;

    __half* Xp; float *H, *h1;
    cudaGetSymbolAddress((void**)&Xp, g_Xp);
    cudaGetSymbolAddress((void**)&H,  g_H);
    cudaGetSymbolAddress((void**)&h1, g_h1);

    cudaFuncSetAttribute(lstm_mma_kernel,     cudaFuncAttributeMaxDynamicSharedMemorySize, LSTM_SMEM);
    cudaFuncSetAttribute(hmma_proj_kernel,    cudaFuncAttributeMaxDynamicSharedMemorySize, PROJ_SMEM);
    cudaFuncSetAttribute(hmma_combine_kernel, cudaFuncAttributeMaxDynamicSharedMemorySize, CMB_SMEM);

    const int TB = 256;
    const int GRID = (NNODE + NODES_B - 1) / NODES_B;   // 139 <= 148: one wave

    // ---- layer 1 ----
    hmma_proj_kernel<<<GRID, NWARP * 32, PROJ_SMEM>>>(x, Wih1, bih1, bhh1, Xp);
    lstm_mma_kernel<<<GRID, NWARP * 32, LSTM_SMEM>>>(Xp, nbr, Whh1, H);
    hmma_combine_kernel<<<GRID, NWARP * 32, CMB_SMEM>>>(x, H, Wself1, Wneigh1, bneigh1, h1);

    // ---- layer 2 ----
    hmma_proj_kernel<<<GRID, NWARP * 32, PROJ_SMEM>>>(h1, Wih2, bih2, bhh2, Xp);
    lstm_mma_kernel<<<GRID, NWARP * 32, LSTM_SMEM>>>(Xp, nbr, Whh2, H);
    out_kernel<<<(NNODE * 32 + TB - 1) / TB, TB>>>(h1, H, Wself2, Wneigh2, bneigh2, out, NNODE);
}